// round 11
// baseline (speedup 1.0000x reference)
#include <cuda_runtime.h>
#include <cuda_bf16.h>
#include <cstdint>
#include <math.h>

#define N_BATCH 16
#define CH 64
#define SCH 128
#define L_IN 8192
#define L_OUT 7682
#define NUM_BLOCKS 16
#define TILE_P 128
#define NTH 256

// Ping-pong fp32 residual buffers.
__device__ float g_bufA[(size_t)N_BATCH * CH * L_IN];
__device__ float g_bufB[(size_t)N_BATCH * CH * L_IN];

// Per-block pre-fragmented bf16 weights. uint4 per (region, kstep, nblock, lane):
//   (hi.b0, hi.b1, lo.b0, lo.b1)  -- exact mma.sync m16n8k16 B-fragment regs.
// uint4 index layout:
//   Wd: (ks8 * 8 + nb8) * 32 + lane   -> [0, 2048)
//   Wr: 2048 + (ks4 * 8 + nb8) * 32 + lane  -> [2048, 3072)
//   Ws: 3072 + (ks4 * 16 + nb16) * 32 + lane -> [3072, 5120)
#define IMG_U32 20480
#define W4_WD 0
#define W4_WR 2048
#define W4_WS 3072
__device__ __align__(128) uint32_t g_Wimg[NUM_BLOCKS * IMG_U32];

// ---- shared memory: A operand only ----
// ldmatrix needs 16B-aligned rows; stride 132 u32 (528B): 4-bank shift/row ->
// conflict-free ldmatrix phases (validated in R9/R10).
#define A_STRIDE_U32 132
#define SMEM_BYTES (128 * A_STRIDE_U32 * 4)   // 67584

__device__ __forceinline__ uint32_t smem_to_u32(const void* p) {
    uint32_t a;
    asm("{ .reg .u64 t; cvta.to.shared.u64 t, %1; cvt.u32.u64 %0, t; }"
        : "=r"(a) : "l"(p));
    return a;
}

__device__ __forceinline__ void ldm_x4(uint32_t* a, uint32_t saddr) {
    asm volatile("ldmatrix.sync.aligned.m8n8.x4.shared.b16 {%0,%1,%2,%3}, [%4];"
                 : "=r"(a[0]), "=r"(a[1]), "=r"(a[2]), "=r"(a[3]) : "r"(saddr));
}

__device__ __forceinline__ void mma16816(float* d, const uint32_t* a,
                                         uint32_t b0, uint32_t b1) {
    asm volatile(
        "mma.sync.aligned.m16n8k16.row.col.f32.bf16.bf16.f32 "
        "{%0,%1,%2,%3}, {%4,%5,%6,%7}, {%8,%9}, {%0,%1,%2,%3};"
        : "+f"(d[0]), "+f"(d[1]), "+f"(d[2]), "+f"(d[3])
        : "r"(a[0]), "r"(a[1]), "r"(a[2]), "r"(a[3]), "r"(b0), "r"(b1));
}

// L2-only load (no L1 allocation): keep L1 for the weight image.
__device__ __forceinline__ float ldcg(const float* p) {
    float v;
    asm volatile("ld.global.cg.f32 %0, [%1];" : "=f"(v) : "l"(p));
    return v;
}

__device__ __forceinline__ uint32_t pack2(__nv_bfloat16 a, __nv_bfloat16 b) {
    __nv_bfloat162 t(a, b);   // a -> low halfword
    return *reinterpret_cast<uint32_t*>(&t);
}

__device__ __forceinline__ void split(float x, __nv_bfloat16& h, __nv_bfloat16& l) {
    h = __float2bfloat16(x);
    l = __float2bfloat16(x - __bfloat162float(h));
}

// g = tanh(y) * sigmoid(y), via a = e^{-y}.
__device__ __forceinline__ float gated(float y) {
    float yc = fminf(fmaxf(y, -15.f), 15.f);
    float a = __expf(-yc);
    float a2 = a * a;
    return __fdividef(1.f - a2, (1.f + a2) * (1.f + a));
}

// ---------------- prep: build per-lane B fragments ----------------
__global__ void prep_weights(const float* __restrict__ Wd,
                             const float* __restrict__ Wr,
                             const float* __restrict__ Ws)
{
    int idx = blockIdx.x * blockDim.x + threadIdx.x;
    if (idx >= NUM_BLOCKS * IMG_U32) return;
    int b = idx / IMG_U32;
    int r = idx % IMG_U32;
    int f = r >> 2;            // uint4 index
    int comp = r & 3;          // 0: hi.b0, 1: hi.b1, 2: lo.b0, 3: lo.b1
    int part = comp >> 1;      // 0 = hi, 1 = lo
    int reg = comp & 1;        // b0 (k=2q..) or b1 (k=2q+8..)
    float w0, w1;
    if (f < W4_WR) {            // Wd region
        int lane = f & 31, nb = (f >> 5) & 7, ks = (f >> 8) & 7;
        int nn = nb * 8 + (lane >> 2), q = lane & 3;
        int k0 = ks * 16 + 2 * q + reg * 8;   // k = ch*2 + tap
        w0 = Wd[(((size_t)b * CH + nn) * CH + (k0 >> 1)) * 2 + (k0 & 1)];
        w1 = Wd[(((size_t)b * CH + nn) * CH + ((k0 + 1) >> 1)) * 2 + ((k0 + 1) & 1)];
    } else if (f < W4_WS) {     // Wr region
        int ff = f - W4_WR;
        int lane = ff & 31, nb = (ff >> 5) & 7, ks = (ff >> 8) & 3;
        int nn = nb * 8 + (lane >> 2), q = lane & 3;
        int k0 = ks * 16 + 2 * q + reg * 8;
        w0 = Wr[((size_t)b * CH + nn) * CH + k0];
        w1 = Wr[((size_t)b * CH + nn) * CH + k0 + 1];
    } else {                    // Ws region
        int ff = f - W4_WS;
        int lane = ff & 31, nb = (ff >> 5) & 15, ks = (ff >> 9) & 3;
        int nn = nb * 8 + (lane >> 2), q = lane & 3;
        int k0 = ks * 16 + 2 * q + reg * 8;
        w0 = Ws[((size_t)b * SCH + nn) * CH + k0];
        w1 = Ws[((size_t)b * SCH + nn) * CH + k0 + 1];
    }
    __nv_bfloat16 h0 = __float2bfloat16(w0);
    __nv_bfloat16 h1 = __float2bfloat16(w1);
    if (part) {
        h0 = __float2bfloat16(w0 - __bfloat162float(h0));
        h1 = __float2bfloat16(w1 - __bfloat162float(h1));
    }
    g_Wimg[(size_t)b * IMG_U32 + r] = pack2(h0, h1);
}

// ---------------- main block kernel (warp MMA, register-resident G) ----------------
__global__ void __launch_bounds__(NTH, 2)
wn_mma_kernel(const float* __restrict__ src, int src_stride,
              float* __restrict__ dst, int dst_stride,
              const uint32_t* __restrict__ wimg,
              float* __restrict__ skip,
              int Lcur, int d, int skip_off, int is_first)
{
    extern __shared__ unsigned char smem[];
    uint32_t* smu = reinterpret_cast<uint32_t*>(smem);
    const uint32_t smem_base = smem_to_u32(smem);
    const int tid = threadIdx.x;
    const int warp = tid >> 5, lane = tid & 31;
    const int n = blockIdx.y;
    const int p0 = blockIdx.x * TILE_P;
    const int Lnew = Lcur - d;

    const uint4* w4 = reinterpret_cast<const uint4*>(wimg);
    const float* srcn = src + (size_t)n * CH * src_stride;

    // ---- build A: [pos][k] bf16, hi u32 cols 0..63, lo 64..127 (L2-only loads) ----
    {
        const int pos = tid & 127, half = tid >> 7;
        const int p = p0 + pos;
        const bool v = (p < Lnew);
#pragma unroll 4
        for (int it = 0; it < 32; it++) {
            int ch = it * 2 + half;
            float x0 = v ? ldcg(srcn + (size_t)ch * src_stride + p) : 0.f;
            float x1 = v ? ldcg(srcn + (size_t)ch * src_stride + p + d) : 0.f;
            __nv_bfloat16 h0, l0, h1, l1;
            split(x0, h0, l0);
            split(x1, h1, l1);
            smu[pos * A_STRIDE_U32 + ch] = pack2(h0, h1);        // k=2ch,2ch+1
            smu[pos * A_STRIDE_U32 + 64 + ch] = pack2(l0, l1);
        }
    }
    __syncthreads();

    const int mrow = warp * 16 + (lane & 15);
    const int r = lane >> 2, q = lane & 3;
    const int row0 = warp * 16 + r;

    // ================= GEMM1: Y[128,64] = X2 * Wd^T (3-term) =================
    float d1[8][4];
#pragma unroll
    for (int a = 0; a < 8; a++)
#pragma unroll
        for (int k = 0; k < 4; k++) d1[a][k] = 0.f;

    {
        const uint32_t a_row = smem_base + mrow * (A_STRIDE_U32 * 4)
                             + ((lane >> 4) * 16);
#pragma unroll
        for (int ks = 0; ks < 8; ks++) {
            uint32_t ah[4], al[4];
            ldm_x4(ah, a_row + ks * 32);
            ldm_x4(al, a_row + 256 + ks * 32);
#pragma unroll
            for (int nb = 0; nb < 8; nb++) {
                uint4 w = __ldg(w4 + W4_WD + (ks * 8 + nb) * 32 + lane);
                mma16816(d1[nb], ah, w.x, w.y);
                mma16816(d1[nb], al, w.x, w.y);
                mma16816(d1[nb], ah, w.z, w.w);
            }
        }
    }

    // ---- epilogue 1 (registers only): gate, hi/lo split, repack as A-fragments ----
    // D-frag of GEMM1 == A-frag of GEMM2 (validated in R9/R10).
    uint32_t gah[4][4], gal[4][4];
#pragma unroll
    for (int nb = 0; nb < 8; nb++)
#pragma unroll
        for (int k = 0; k < 4; k++) d1[nb][k] = gated(d1[nb][k]);
#pragma unroll
    for (int ks = 0; ks < 4; ks++) {
#pragma unroll
        for (int half = 0; half < 2; half++) {   // half: nb = 2ks / 2ks+1
            int nb = 2 * ks + half;
            __nv_bfloat16 h0, l0, h1, l1, h2, l2, h3, l3;
            split(d1[nb][0], h0, l0);
            split(d1[nb][1], h1, l1);
            split(d1[nb][2], h2, l2);
            split(d1[nb][3], h3, l3);
            gah[ks][2 * half]     = pack2(h0, h1);
            gah[ks][2 * half + 1] = pack2(h2, h3);
            gal[ks][2 * half]     = pack2(l0, l1);
            gal[ks][2 * half + 1] = pack2(l2, l3);
        }
    }

    const int pA = p0 + row0;
    const int pB = pA + 8;
    const bool vA = (pA < Lnew), vB = (pB < Lnew);

    // ================= GEMM2a: res[128,64] (3-term) + direct store =================
    {
        float dr[8][4];
#pragma unroll
        for (int a = 0; a < 8; a++)
#pragma unroll
            for (int k = 0; k < 4; k++) dr[a][k] = 0.f;

#pragma unroll
        for (int ks = 0; ks < 4; ks++) {
#pragma unroll
            for (int nb = 0; nb < 8; nb++) {
                uint4 w = __ldg(w4 + W4_WR + (ks * 8 + nb) * 32 + lane);
                mma16816(dr[nb], gah[ks], w.x, w.y);
                mma16816(dr[nb], gal[ks], w.x, w.y);
                mma16816(dr[nb], gah[ks], w.z, w.w);
            }
        }
        // direct store with residual add (residual reads L2-only)
#pragma unroll
        for (int nb = 0; nb < 8; nb++) {
            int c = nb * 8 + 2 * q;
            if (vA) {
                dst[((size_t)n * CH + c) * dst_stride + pA] =
                    dr[nb][0] + ldcg(srcn + (size_t)c * src_stride + pA + d);
                dst[((size_t)n * CH + c + 1) * dst_stride + pA] =
                    dr[nb][1] + ldcg(srcn + (size_t)(c + 1) * src_stride + pA + d);
            }
            if (vB) {
                dst[((size_t)n * CH + c) * dst_stride + pB] =
                    dr[nb][2] + ldcg(srcn + (size_t)c * src_stride + pB + d);
                dst[((size_t)n * CH + c + 1) * dst_stride + pB] =
                    dr[nb][3] + ldcg(srcn + (size_t)(c + 1) * src_stride + pB + d);
            }
        }
    }

    // ================= GEMM2b: skip[128,128] in two n-halves =================
    const int jA = pA - skip_off;
    const int jB = pB - skip_off;
#pragma unroll
    for (int h = 0; h < 2; h++) {
        float ds[8][4];
#pragma unroll
        for (int a = 0; a < 8; a++)
#pragma unroll
            for (int k = 0; k < 4; k++) ds[a][k] = 0.f;

#pragma unroll
        for (int ks = 0; ks < 4; ks++) {
#pragma unroll
            for (int nb = 0; nb < 8; nb++) {
                int nbg = h * 8 + nb;
                uint4 w = __ldg(w4 + W4_WS + (ks * 16 + nbg) * 32 + lane);
                mma16816(ds[nb], gah[ks], w.x, w.y);
                mma16816(ds[nb], gal[ks], w.x, w.y);
                mma16816(ds[nb], gah[ks], w.z, w.w);
            }
        }
#pragma unroll
        for (int nb = 0; nb < 8; nb++) {
            int c = h * 64 + nb * 8 + 2 * q;
            float* r0p = skip + ((size_t)n * SCH + c) * L_OUT;
            float* r1p = skip + ((size_t)n * SCH + c + 1) * L_OUT;
            if (vA && jA >= 0) {
                if (is_first) { r0p[jA] = ds[nb][0]; r1p[jA] = ds[nb][1]; }
                else          { r0p[jA] += ds[nb][0]; r1p[jA] += ds[nb][1]; }
            }
            if (vB && jB >= 0) {
                if (is_first) { r0p[jB] = ds[nb][2]; r1p[jB] = ds[nb][3]; }
                else          { r0p[jB] += ds[nb][2]; r1p[jB] += ds[nb][3]; }
            }
        }
    }
}

extern "C" void kernel_launch(void* const* d_in, const int* in_sizes, int n_in,
                              void* d_out, int out_size)
{
    const float* x  = (const float*)d_in[0];  // (16, 64, 8192)
    const float* Wd = (const float*)d_in[1];  // (16, 64, 64, 2)
    const float* Wr = (const float*)d_in[2];  // (16, 64, 64)
    const float* Ws = (const float*)d_in[3];  // (16, 128, 64)

    float* out  = (float*)d_out;                                   // (16, 64, 7682)
    float* skip = (float*)d_out + (size_t)N_BATCH * CH * L_OUT;    // (16, 128, 7682)

    float *bufA = nullptr, *bufB = nullptr;
    uint32_t* wimg = nullptr;
    cudaGetSymbolAddress((void**)&bufA, g_bufA);
    cudaGetSymbolAddress((void**)&bufB, g_bufB);
    cudaGetSymbolAddress((void**)&wimg, g_Wimg);
    cudaFuncSetAttribute(wn_mma_kernel,
                         cudaFuncAttributeMaxDynamicSharedMemorySize, SMEM_BYTES);

    // Build per-lane weight fragments once per replay.
    {
        int total = NUM_BLOCKS * IMG_U32;
        prep_weights<<<(total + 255) / 256, 256>>>(Wd, Wr, Ws);
    }

    const int dil[NUM_BLOCKS] = {1, 2, 4, 8, 16, 32, 64, 128,
                                 1, 2, 4, 8, 16, 32, 64, 128};

    const float* src = x;
    int src_stride = L_IN;
    int Lcur = L_IN;

    for (int i = 0; i < NUM_BLOCKS; i++) {
        int d = dil[i];
        int Lnew = Lcur - d;
        float* dst;
        int dst_stride;
        if (i == NUM_BLOCKS - 1) { dst = out; dst_stride = L_OUT; }
        else                     { dst = (i & 1) ? bufB : bufA; dst_stride = L_IN; }

        dim3 grid((Lnew + TILE_P - 1) / TILE_P, N_BATCH);
        wn_mma_kernel<<<grid, NTH, SMEM_BYTES>>>(
            src, src_stride, dst, dst_stride,
            wimg + (size_t)i * IMG_U32,
            skip, Lcur, d, Lnew - L_OUT, (i == 0) ? 1 : 0);

        src = dst;
        src_stride = dst_stride;
        Lcur = Lnew;
    }
}

// round 12
// speedup vs baseline: 1.0302x; 1.0302x over previous
#include <cuda_runtime.h>
#include <cuda_bf16.h>
#include <cstdint>
#include <math.h>

#define N_BATCH 16
#define CH 64
#define SCH 128
#define L_IN 8192
#define L_OUT 7682
#define NUM_BLOCKS 16
#define TILE_P 128
#define NTH 256

// Ping-pong fp32 residual buffers.
__device__ float g_bufA[(size_t)N_BATCH * CH * L_IN];
__device__ float g_bufB[(size_t)N_BATCH * CH * L_IN];

// Per-block pre-fragmented bf16 weights. uint4 per (region, kstep, nblock, lane):
//   (hi.b0, hi.b1, lo.b0, lo.b1)  -- exact mma.sync m16n8k16 B-fragment regs.
#define IMG_U32 20480
#define W4_WD 0
#define W4_WR 2048
#define W4_WS 3072
__device__ __align__(128) uint32_t g_Wimg[NUM_BLOCKS * IMG_U32];

// ---- shared memory ----
// A tile: 128 rows x 132 u32 (stride validated conflict-free for ldmatrix).
// After GEMM1, each warp's 2112-u32 A band is dead and is reused for that
// warp's G fragments (thread-private: each thread reads only what it wrote).
// Residual plane: X1 tap cached fp32, stride 65 (odd -> conflict-free STS).
#define A_STRIDE_U32 132
#define A_U32 (128 * A_STRIDE_U32)          // 16896
#define RES_OFF A_U32                       // float/u32 index base
#define RES_STRIDE 65
#define SMEM_BYTES ((A_U32 + 128 * RES_STRIDE) * 4)   // 100864

__device__ __forceinline__ uint32_t smem_to_u32(const void* p) {
    uint32_t a;
    asm("{ .reg .u64 t; cvta.to.shared.u64 t, %1; cvt.u32.u64 %0, t; }"
        : "=r"(a) : "l"(p));
    return a;
}

__device__ __forceinline__ void ldm_x4(uint32_t* a, uint32_t saddr) {
    asm volatile("ldmatrix.sync.aligned.m8n8.x4.shared.b16 {%0,%1,%2,%3}, [%4];"
                 : "=r"(a[0]), "=r"(a[1]), "=r"(a[2]), "=r"(a[3]) : "r"(saddr));
}

__device__ __forceinline__ void mma16816(float* d, const uint32_t* a,
                                         uint32_t b0, uint32_t b1) {
    asm volatile(
        "mma.sync.aligned.m16n8k16.row.col.f32.bf16.bf16.f32 "
        "{%0,%1,%2,%3}, {%4,%5,%6,%7}, {%8,%9}, {%0,%1,%2,%3};"
        : "+f"(d[0]), "+f"(d[1]), "+f"(d[2]), "+f"(d[3])
        : "r"(a[0]), "r"(a[1]), "r"(a[2]), "r"(a[3]), "r"(b0), "r"(b1));
}

__device__ __forceinline__ uint32_t pack2(__nv_bfloat16 a, __nv_bfloat16 b) {
    __nv_bfloat162 t(a, b);   // a -> low halfword
    return *reinterpret_cast<uint32_t*>(&t);
}

__device__ __forceinline__ void split(float x, __nv_bfloat16& h, __nv_bfloat16& l) {
    h = __float2bfloat16(x);
    l = __float2bfloat16(x - __bfloat162float(h));
}

// g = tanh(y) * sigmoid(y), via a = e^{-y}.
__device__ __forceinline__ float gated(float y) {
    float yc = fminf(fmaxf(y, -15.f), 15.f);
    float a = __expf(-yc);
    float a2 = a * a;
    return __fdividef(1.f - a2, (1.f + a2) * (1.f + a));
}

// ---------------- prep: build per-lane B fragments (uint4 layout, R11-validated) ----------------
__global__ void prep_weights(const float* __restrict__ Wd,
                             const float* __restrict__ Wr,
                             const float* __restrict__ Ws)
{
    int idx = blockIdx.x * blockDim.x + threadIdx.x;
    if (idx >= NUM_BLOCKS * IMG_U32) return;
    int b = idx / IMG_U32;
    int r = idx % IMG_U32;
    int f = r >> 2;            // uint4 index
    int comp = r & 3;          // 0: hi.b0, 1: hi.b1, 2: lo.b0, 3: lo.b1
    int part = comp >> 1;
    int reg = comp & 1;
    float w0, w1;
    if (f < W4_WR) {            // Wd region
        int lane = f & 31, nb = (f >> 5) & 7, ks = (f >> 8) & 7;
        int nn = nb * 8 + (lane >> 2), q = lane & 3;
        int k0 = ks * 16 + 2 * q + reg * 8;   // k = ch*2 + tap
        w0 = Wd[(((size_t)b * CH + nn) * CH + (k0 >> 1)) * 2 + (k0 & 1)];
        w1 = Wd[(((size_t)b * CH + nn) * CH + ((k0 + 1) >> 1)) * 2 + ((k0 + 1) & 1)];
    } else if (f < W4_WS) {     // Wr region
        int ff = f - W4_WR;
        int lane = ff & 31, nb = (ff >> 5) & 7, ks = (ff >> 8) & 3;
        int nn = nb * 8 + (lane >> 2), q = lane & 3;
        int k0 = ks * 16 + 2 * q + reg * 8;
        w0 = Wr[((size_t)b * CH + nn) * CH + k0];
        w1 = Wr[((size_t)b * CH + nn) * CH + k0 + 1];
    } else {                    // Ws region
        int ff = f - W4_WS;
        int lane = ff & 31, nb = (ff >> 5) & 15, ks = (ff >> 9) & 3;
        int nn = nb * 8 + (lane >> 2), q = lane & 3;
        int k0 = ks * 16 + 2 * q + reg * 8;
        w0 = Ws[((size_t)b * SCH + nn) * CH + k0];
        w1 = Ws[((size_t)b * SCH + nn) * CH + k0 + 1];
    }
    __nv_bfloat16 h0 = __float2bfloat16(w0);
    __nv_bfloat16 h1 = __float2bfloat16(w1);
    if (part) {
        h0 = __float2bfloat16(w0 - __bfloat162float(h0));
        h1 = __float2bfloat16(w1 - __bfloat162float(h1));
    }
    g_Wimg[(size_t)b * IMG_U32 + r] = pack2(h0, h1);
}

// ---------------- main block kernel ----------------
__global__ void __launch_bounds__(NTH, 2)
wn_mma_kernel(const float* __restrict__ src, int src_stride,
              float* __restrict__ dst, int dst_stride,
              const uint32_t* __restrict__ wimg,
              float* __restrict__ skip,
              int Lcur, int d, int skip_off, int is_first)
{
    extern __shared__ unsigned char smem[];
    uint32_t* smu = reinterpret_cast<uint32_t*>(smem);
    float* smf = reinterpret_cast<float*>(smem);
    const uint32_t smem_base = smem_to_u32(smem);
    const int tid = threadIdx.x;
    const int warp = tid >> 5, lane = tid & 31;
    const int n = blockIdx.y;
    const int p0 = blockIdx.x * TILE_P;
    const int Lnew = Lcur - d;

    const uint4* w4 = reinterpret_cast<const uint4*>(wimg);
    const float* srcn = src + (size_t)n * CH * src_stride;

    // ---- build A: [pos][k] bf16, hi u32 cols 0..63, lo 64..127; cache X1 fp32 ----
    {
        const int pos = tid & 127, half = tid >> 7;
        const int p = p0 + pos;
        const bool v = (p < Lnew);
#pragma unroll 4
        for (int it = 0; it < 32; it++) {
            int ch = it * 2 + half;
            float x0 = v ? __ldg(srcn + (size_t)ch * src_stride + p) : 0.f;
            float x1 = v ? __ldg(srcn + (size_t)ch * src_stride + p + d) : 0.f;
            __nv_bfloat16 h0, l0, h1, l1;
            split(x0, h0, l0);
            split(x1, h1, l1);
            smu[pos * A_STRIDE_U32 + ch] = pack2(h0, h1);        // k=2ch,2ch+1
            smu[pos * A_STRIDE_U32 + 64 + ch] = pack2(l0, l1);
            smf[RES_OFF + pos * RES_STRIDE + ch] = x1;           // residual tap
        }
    }
    __syncthreads();

    const int mrow = warp * 16 + (lane & 15);
    const int r = lane >> 2, q = lane & 3;
    const int row0 = warp * 16 + r;
    // per-warp, thread-private G region inside the warp's dead A band
    const int gbase = warp * 2112 + lane;   // entries at gbase + (ks*8+i)*64

    // ================= GEMM1: Y[128,64] = X2 * Wd^T (3-term) =================
    float d1[8][4];
#pragma unroll
    for (int a = 0; a < 8; a++)
#pragma unroll
        for (int k = 0; k < 4; k++) d1[a][k] = 0.f;

    {
        const uint32_t a_row = smem_base + mrow * (A_STRIDE_U32 * 4)
                             + ((lane >> 4) * 16);
#pragma unroll
        for (int ks = 0; ks < 8; ks++) {
            uint4 wa[4];
#pragma unroll
            for (int j = 0; j < 4; j++)
                wa[j] = __ldg(w4 + W4_WD + (ks * 8 + j) * 32 + lane);
            uint32_t ah[4], al[4];
            ldm_x4(ah, a_row + ks * 32);
            ldm_x4(al, a_row + 256 + ks * 32);
            uint4 wb[4];
#pragma unroll
            for (int j = 0; j < 4; j++)
                wb[j] = __ldg(w4 + W4_WD + (ks * 8 + 4 + j) * 32 + lane);
#pragma unroll
            for (int j = 0; j < 4; j++) {
                mma16816(d1[j], ah, wa[j].x, wa[j].y);
                mma16816(d1[j], al, wa[j].x, wa[j].y);
                mma16816(d1[j], ah, wa[j].z, wa[j].w);
            }
#pragma unroll
            for (int j = 0; j < 4; j++) {
                mma16816(d1[4 + j], ah, wb[j].x, wb[j].y);
                mma16816(d1[4 + j], al, wb[j].x, wb[j].y);
                mma16816(d1[4 + j], ah, wb[j].z, wb[j].w);
            }
        }
    }

    // ---- epilogue 1: gate, hi/lo split, store A-fragments to thread-private smem ----
    // D-frag of GEMM1 == A-frag of GEMM2 (validated R9/R10).
#pragma unroll
    for (int nb = 0; nb < 8; nb++)
#pragma unroll
        for (int k = 0; k < 4; k++) d1[nb][k] = gated(d1[nb][k]);
#pragma unroll
    for (int ks = 0; ks < 4; ks++) {
#pragma unroll
        for (int half = 0; half < 2; half++) {   // nb = 2ks+half
            int nb = 2 * ks + half;
            __nv_bfloat16 h0, l0, h1, l1, h2, l2, h3, l3;
            split(d1[nb][0], h0, l0);
            split(d1[nb][1], h1, l1);
            split(d1[nb][2], h2, l2);
            split(d1[nb][3], h3, l3);
            smu[gbase + (ks * 8 + 2 * half) * 64]       = pack2(h0, h1);
            smu[gbase + (ks * 8 + 2 * half + 1) * 64]   = pack2(h2, h3);
            smu[gbase + (ks * 8 + 4 + 2 * half) * 64]   = pack2(l0, l1);
            smu[gbase + (ks * 8 + 4 + 2 * half + 1) * 64] = pack2(l2, l3);
        }
    }

    const int pA = p0 + row0;
    const int pB = pA + 8;
    const bool vA = (pA < Lnew), vB = (pB < Lnew);

    // ================= GEMM2a: res[128,64] (3-term) + direct store =================
    {
        float dr[8][4];
#pragma unroll
        for (int a = 0; a < 8; a++)
#pragma unroll
            for (int k = 0; k < 4; k++) dr[a][k] = 0.f;

#pragma unroll
        for (int ks = 0; ks < 4; ks++) {
            uint32_t gah[4], gal[4];
#pragma unroll
            for (int j = 0; j < 4; j++) {
                gah[j] = smu[gbase + (ks * 8 + j) * 64];
                gal[j] = smu[gbase + (ks * 8 + 4 + j) * 64];
            }
#pragma unroll
            for (int nb = 0; nb < 8; nb++) {
                uint4 w = __ldg(w4 + W4_WR + (ks * 8 + nb) * 32 + lane);
                mma16816(dr[nb], gah, w.x, w.y);
                mma16816(dr[nb], gal, w.x, w.y);
                mma16816(dr[nb], gah, w.z, w.w);
            }
        }
        // direct store with residual add (residual from smem cache)
#pragma unroll
        for (int nb = 0; nb < 8; nb++) {
            int c = nb * 8 + 2 * q;
            if (vA) {
                dst[((size_t)n * CH + c) * dst_stride + pA] =
                    dr[nb][0] + smf[RES_OFF + row0 * RES_STRIDE + c];
                dst[((size_t)n * CH + c + 1) * dst_stride + pA] =
                    dr[nb][1] + smf[RES_OFF + row0 * RES_STRIDE + c + 1];
            }
            if (vB) {
                dst[((size_t)n * CH + c) * dst_stride + pB] =
                    dr[nb][2] + smf[RES_OFF + (row0 + 8) * RES_STRIDE + c];
                dst[((size_t)n * CH + c + 1) * dst_stride + pB] =
                    dr[nb][3] + smf[RES_OFF + (row0 + 8) * RES_STRIDE + c + 1];
            }
        }
    }

    // ================= GEMM2b: skip[128,128] in two n-halves =================
    const int jA = pA - skip_off;
    const int jB = pB - skip_off;
#pragma unroll
    for (int h = 0; h < 2; h++) {
        float ds[8][4];
#pragma unroll
        for (int a = 0; a < 8; a++)
#pragma unroll
            for (int k = 0; k < 4; k++) ds[a][k] = 0.f;

#pragma unroll
        for (int ks = 0; ks < 4; ks++) {
            uint32_t gah[4], gal[4];
#pragma unroll
            for (int j = 0; j < 4; j++) {
                gah[j] = smu[gbase + (ks * 8 + j) * 64];
                gal[j] = smu[gbase + (ks * 8 + 4 + j) * 64];
            }
#pragma unroll
            for (int nb = 0; nb < 8; nb++) {
                int nbg = h * 8 + nb;
                uint4 w = __ldg(w4 + W4_WS + (ks * 16 + nbg) * 32 + lane);
                mma16816(ds[nb], gah, w.x, w.y);
                mma16816(ds[nb], gal, w.x, w.y);
                mma16816(ds[nb], gah, w.z, w.w);
            }
        }
#pragma unroll
        for (int nb = 0; nb < 8; nb++) {
            int c = h * 64 + nb * 8 + 2 * q;
            float* r0p = skip + ((size_t)n * SCH + c) * L_OUT;
            float* r1p = skip + ((size_t)n * SCH + c + 1) * L_OUT;
            if (vA && jA >= 0) {
                if (is_first) { r0p[jA] = ds[nb][0]; r1p[jA] = ds[nb][1]; }
                else          { r0p[jA] += ds[nb][0]; r1p[jA] += ds[nb][1]; }
            }
            if (vB && jB >= 0) {
                if (is_first) { r0p[jB] = ds[nb][2]; r1p[jB] = ds[nb][3]; }
                else          { r0p[jB] += ds[nb][2]; r1p[jB] += ds[nb][3]; }
            }
        }
    }
}

extern "C" void kernel_launch(void* const* d_in, const int* in_sizes, int n_in,
                              void* d_out, int out_size)
{
    const float* x  = (const float*)d_in[0];  // (16, 64, 8192)
    const float* Wd = (const float*)d_in[1];  // (16, 64, 64, 2)
    const float* Wr = (const float*)d_in[2];  // (16, 64, 64)
    const float* Ws = (const float*)d_in[3];  // (16, 128, 64)

    float* out  = (float*)d_out;                                   // (16, 64, 7682)
    float* skip = (float*)d_out + (size_t)N_BATCH * CH * L_OUT;    // (16, 128, 7682)

    float *bufA = nullptr, *bufB = nullptr;
    uint32_t* wimg = nullptr;
    cudaGetSymbolAddress((void**)&bufA, g_bufA);
    cudaGetSymbolAddress((void**)&bufB, g_bufB);
    cudaGetSymbolAddress((void**)&wimg, g_Wimg);
    cudaFuncSetAttribute(wn_mma_kernel,
                         cudaFuncAttributeMaxDynamicSharedMemorySize, SMEM_BYTES);

    // Build per-lane weight fragments once per replay.
    {
        int total = NUM_BLOCKS * IMG_U32;
        prep_weights<<<(total + 255) / 256, 256>>>(Wd, Wr, Ws);
    }

    const int dil[NUM_BLOCKS] = {1, 2, 4, 8, 16, 32, 64, 128,
                                 1, 2, 4, 8, 16, 32, 64, 128};

    const float* src = x;
    int src_stride = L_IN;
    int Lcur = L_IN;

    for (int i = 0; i < NUM_BLOCKS; i++) {
        int d = dil[i];
        int Lnew = Lcur - d;
        float* dst;
        int dst_stride;
        if (i == NUM_BLOCKS - 1) { dst = out; dst_stride = L_OUT; }
        else                     { dst = (i & 1) ? bufB : bufA; dst_stride = L_IN; }

        dim3 grid((Lnew + TILE_P - 1) / TILE_P, N_BATCH);
        wn_mma_kernel<<<grid, NTH, SMEM_BYTES>>>(
            src, src_stride, dst, dst_stride,
            wimg + (size_t)i * IMG_U32,
            skip, Lcur, d, Lnew - L_OUT, (i == 0) ? 1 : 0);

        src = dst;
        src_stride = dst_stride;
        Lcur = Lnew;
    }
}

// round 13
// speedup vs baseline: 3.0300x; 2.9412x over previous
#include <cuda_runtime.h>
#include <cuda_bf16.h>
#include <cstdint>
#include <math.h>

#define N_BATCH 16
#define CH 64
#define SCH 128
#define L_IN 8192
#define L_OUT 7682
#define NUM_BLOCKS 16
#define TILE_P 128
#define NTH 256

// Ping-pong fp32 residual buffers.
__device__ float g_bufA[(size_t)N_BATCH * CH * L_IN];
__device__ float g_bufB[(size_t)N_BATCH * CH * L_IN];

// Per-block pre-fragmented bf16 weights. uint4 per (region, kstep, nblock, lane):
//   (hi.b0, hi.b1, lo.b0, lo.b1)  -- exact mma.sync m16n8k16 B-fragment regs.
#define IMG_U32 20480
#define W4_WD 0
#define W4_WR 2048
#define W4_WS 3072
__device__ __align__(128) uint32_t g_Wimg[NUM_BLOCKS * IMG_U32];

// ---- shared memory ----
#define A_STRIDE_U32 132
#define A_U32 (128 * A_STRIDE_U32)          // 16896
#define RES_OFF A_U32
#define RES_STRIDE 65
#define SMEM_BYTES ((A_U32 + 128 * RES_STRIDE) * 4)   // 100864

__device__ __forceinline__ uint32_t smem_to_u32(const void* p) {
    uint32_t a;
    asm("{ .reg .u64 t; cvta.to.shared.u64 t, %1; cvt.u32.u64 %0, t; }"
        : "=r"(a) : "l"(p));
    return a;
}

__device__ __forceinline__ void ldm_x4(uint32_t* a, uint32_t saddr) {
    asm volatile("ldmatrix.sync.aligned.m8n8.x4.shared.b16 {%0,%1,%2,%3}, [%4];"
                 : "=r"(a[0]), "=r"(a[1]), "=r"(a[2]), "=r"(a[3]) : "r"(saddr));
}

__device__ __forceinline__ void mma16816(float* d, const uint32_t* a,
                                         uint32_t b0, uint32_t b1) {
    asm volatile(
        "mma.sync.aligned.m16n8k16.row.col.f32.bf16.bf16.f32 "
        "{%0,%1,%2,%3}, {%4,%5,%6,%7}, {%8,%9}, {%0,%1,%2,%3};"
        : "+f"(d[0]), "+f"(d[1]), "+f"(d[2]), "+f"(d[3])
        : "r"(a[0]), "r"(a[1]), "r"(a[2]), "r"(a[3]), "r"(b0), "r"(b1));
}

// Fire-and-forget global float add (REDG): no return-trip latency.
__device__ __forceinline__ void redadd(float* p, float v) {
    asm volatile("red.global.add.f32 [%0], %1;" :: "l"(p), "f"(v) : "memory");
}

__device__ __forceinline__ uint32_t pack2(__nv_bfloat16 a, __nv_bfloat16 b) {
    __nv_bfloat162 t(a, b);   // a -> low halfword
    return *reinterpret_cast<uint32_t*>(&t);
}

__device__ __forceinline__ void split(float x, __nv_bfloat16& h, __nv_bfloat16& l) {
    h = __float2bfloat16(x);
    l = __float2bfloat16(x - __bfloat162float(h));
}

// g = tanh(y) * sigmoid(y), via a = e^{-y}.
__device__ __forceinline__ float gated(float y) {
    float yc = fminf(fmaxf(y, -15.f), 15.f);
    float a = __expf(-yc);
    float a2 = a * a;
    return __fdividef(1.f - a2, (1.f + a2) * (1.f + a));
}

// ---------------- prep: build per-lane B fragments (uint4 layout, validated) ----------------
__global__ void prep_weights(const float* __restrict__ Wd,
                             const float* __restrict__ Wr,
                             const float* __restrict__ Ws)
{
    int idx = blockIdx.x * blockDim.x + threadIdx.x;
    if (idx >= NUM_BLOCKS * IMG_U32) return;
    int b = idx / IMG_U32;
    int r = idx % IMG_U32;
    int f = r >> 2;
    int comp = r & 3;
    int part = comp >> 1;
    int reg = comp & 1;
    float w0, w1;
    if (f < W4_WR) {            // Wd region
        int lane = f & 31, nb = (f >> 5) & 7, ks = (f >> 8) & 7;
        int nn = nb * 8 + (lane >> 2), q = lane & 3;
        int k0 = ks * 16 + 2 * q + reg * 8;   // k = ch*2 + tap
        w0 = Wd[(((size_t)b * CH + nn) * CH + (k0 >> 1)) * 2 + (k0 & 1)];
        w1 = Wd[(((size_t)b * CH + nn) * CH + ((k0 + 1) >> 1)) * 2 + ((k0 + 1) & 1)];
    } else if (f < W4_WS) {     // Wr region
        int ff = f - W4_WR;
        int lane = ff & 31, nb = (ff >> 5) & 7, ks = (ff >> 8) & 3;
        int nn = nb * 8 + (lane >> 2), q = lane & 3;
        int k0 = ks * 16 + 2 * q + reg * 8;
        w0 = Wr[((size_t)b * CH + nn) * CH + k0];
        w1 = Wr[((size_t)b * CH + nn) * CH + k0 + 1];
    } else {                    // Ws region
        int ff = f - W4_WS;
        int lane = ff & 31, nb = (ff >> 5) & 15, ks = (ff >> 9) & 3;
        int nn = nb * 8 + (lane >> 2), q = lane & 3;
        int k0 = ks * 16 + 2 * q + reg * 8;
        w0 = Ws[((size_t)b * SCH + nn) * CH + k0];
        w1 = Ws[((size_t)b * SCH + nn) * CH + k0 + 1];
    }
    __nv_bfloat16 h0 = __float2bfloat16(w0);
    __nv_bfloat16 h1 = __float2bfloat16(w1);
    if (part) {
        h0 = __float2bfloat16(w0 - __bfloat162float(h0));
        h1 = __float2bfloat16(w1 - __bfloat162float(h1));
    }
    g_Wimg[(size_t)b * IMG_U32 + r] = pack2(h0, h1);
}

// ---------------- main block kernel ----------------
__global__ void __launch_bounds__(NTH, 2)
wn_mma_kernel(const float* __restrict__ src, int src_stride,
              float* __restrict__ dst, int dst_stride,
              const uint32_t* __restrict__ wimg,
              float* __restrict__ skip,
              int Lcur, int d, int skip_off, int is_first)
{
    extern __shared__ unsigned char smem[];
    uint32_t* smu = reinterpret_cast<uint32_t*>(smem);
    float* smf = reinterpret_cast<float*>(smem);
    const uint32_t smem_base = smem_to_u32(smem);
    const int tid = threadIdx.x;
    const int warp = tid >> 5, lane = tid & 31;
    const int n = blockIdx.y;
    const int p0 = blockIdx.x * TILE_P;
    const int Lnew = Lcur - d;

    const uint4* w4 = reinterpret_cast<const uint4*>(wimg);
    const float* srcn = src + (size_t)n * CH * src_stride;

    // A-build thread mapping
    const int pos = tid & 127, half = tid >> 7;
    const int pld = p0 + pos;
    const bool vld = (pld < Lnew);

    // build stage g: channels 8g .. 8g+7 (this thread: ch = 8g + 2j + half)
    auto build_stage = [&](int g) {
#pragma unroll
        for (int j = 0; j < 4; j++) {
            int ch = 8 * g + 2 * j + half;
            float x0 = vld ? __ldg(srcn + (size_t)ch * src_stride + pld) : 0.f;
            float x1 = vld ? __ldg(srcn + (size_t)ch * src_stride + pld + d) : 0.f;
            __nv_bfloat16 h0, l0, h1, l1;
            split(x0, h0, l0);
            split(x1, h1, l1);
            smu[pos * A_STRIDE_U32 + ch] = pack2(h0, h1);        // k=2ch,2ch+1
            smu[pos * A_STRIDE_U32 + 64 + ch] = pack2(l0, l1);
            smf[RES_OFF + pos * RES_STRIDE + ch] = x1;           // residual tap
        }
    };

    const int mrow = warp * 16 + (lane & 15);
    const int r = lane >> 2, q = lane & 3;
    const int row0 = warp * 16 + r;
    // per-warp, thread-private G region inside the warp's dead A band
    const int gbase = warp * 2112 + lane;

    // ================= GEMM1 pipelined with A-build =================
    float d1[8][4];
#pragma unroll
    for (int a = 0; a < 8; a++)
#pragma unroll
        for (int k = 0; k < 4; k++) d1[a][k] = 0.f;

    build_stage(0);
    __syncthreads();

    {
        const uint32_t a_row = smem_base + mrow * (A_STRIDE_U32 * 4)
                             + ((lane >> 4) * 16);
#pragma unroll
        for (int ks = 0; ks < 8; ks++) {
            // prefetch next channel group's X while this group's MMAs run
            if (ks < 7) build_stage(ks + 1);

            uint4 wa[4], wb[4];
#pragma unroll
            for (int j = 0; j < 4; j++)
                wa[j] = __ldg(w4 + W4_WD + (ks * 8 + j) * 32 + lane);
#pragma unroll
            for (int j = 0; j < 4; j++)
                wb[j] = __ldg(w4 + W4_WD + (ks * 8 + 4 + j) * 32 + lane);
            uint32_t ah[4], al[4];
            ldm_x4(ah, a_row + ks * 32);
            ldm_x4(al, a_row + 256 + ks * 32);
#pragma unroll
            for (int j = 0; j < 4; j++) {
                mma16816(d1[j], ah, wa[j].x, wa[j].y);
                mma16816(d1[j], al, wa[j].x, wa[j].y);
                mma16816(d1[j], ah, wa[j].z, wa[j].w);
            }
#pragma unroll
            for (int j = 0; j < 4; j++) {
                mma16816(d1[4 + j], ah, wb[j].x, wb[j].y);
                mma16816(d1[4 + j], al, wb[j].x, wb[j].y);
                mma16816(d1[4 + j], ah, wb[j].z, wb[j].w);
            }
            __syncthreads();
        }
    }

    // ---- epilogue 1: gate, hi/lo split, store A-fragments to thread-private smem ----
#pragma unroll
    for (int nb = 0; nb < 8; nb++)
#pragma unroll
        for (int k = 0; k < 4; k++) d1[nb][k] = gated(d1[nb][k]);
#pragma unroll
    for (int ks = 0; ks < 4; ks++) {
#pragma unroll
        for (int hh = 0; hh < 2; hh++) {   // nb = 2ks+hh
            int nb = 2 * ks + hh;
            __nv_bfloat16 h0, l0, h1, l1, h2, l2, h3, l3;
            split(d1[nb][0], h0, l0);
            split(d1[nb][1], h1, l1);
            split(d1[nb][2], h2, l2);
            split(d1[nb][3], h3, l3);
            smu[gbase + (ks * 8 + 2 * hh) * 64]         = pack2(h0, h1);
            smu[gbase + (ks * 8 + 2 * hh + 1) * 64]     = pack2(h2, h3);
            smu[gbase + (ks * 8 + 4 + 2 * hh) * 64]     = pack2(l0, l1);
            smu[gbase + (ks * 8 + 4 + 2 * hh + 1) * 64] = pack2(l2, l3);
        }
    }

    const int pA = p0 + row0;
    const int pB = pA + 8;
    const bool vA = (pA < Lnew), vB = (pB < Lnew);

    // ================= GEMM2a: res[128,64] (3-term) + direct store =================
    {
        float dr[8][4];
#pragma unroll
        for (int a = 0; a < 8; a++)
#pragma unroll
            for (int k = 0; k < 4; k++) dr[a][k] = 0.f;

#pragma unroll
        for (int ks = 0; ks < 4; ks++) {
            uint32_t gah[4], gal[4];
#pragma unroll
            for (int j = 0; j < 4; j++) {
                gah[j] = smu[gbase + (ks * 8 + j) * 64];
                gal[j] = smu[gbase + (ks * 8 + 4 + j) * 64];
            }
#pragma unroll
            for (int nb = 0; nb < 8; nb++) {
                uint4 w = __ldg(w4 + W4_WR + (ks * 8 + nb) * 32 + lane);
                mma16816(dr[nb], gah, w.x, w.y);
                mma16816(dr[nb], gal, w.x, w.y);
                mma16816(dr[nb], gah, w.z, w.w);
            }
        }
        // direct store with residual add (residual from smem cache)
#pragma unroll
        for (int nb = 0; nb < 8; nb++) {
            int c = nb * 8 + 2 * q;
            if (vA) {
                dst[((size_t)n * CH + c) * dst_stride + pA] =
                    dr[nb][0] + smf[RES_OFF + row0 * RES_STRIDE + c];
                dst[((size_t)n * CH + c + 1) * dst_stride + pA] =
                    dr[nb][1] + smf[RES_OFF + row0 * RES_STRIDE + c + 1];
            }
            if (vB) {
                dst[((size_t)n * CH + c) * dst_stride + pB] =
                    dr[nb][2] + smf[RES_OFF + (row0 + 8) * RES_STRIDE + c];
                dst[((size_t)n * CH + c + 1) * dst_stride + pB] =
                    dr[nb][3] + smf[RES_OFF + (row0 + 8) * RES_STRIDE + c + 1];
            }
        }
    }

    // ================= GEMM2b: skip[128,128] in two n-halves =================
    // Skip accumulation via red.global.add (fire-and-forget; no RMW latency).
    const int jA = pA - skip_off;
    const int jB = pB - skip_off;
#pragma unroll
    for (int h = 0; h < 2; h++) {
        float ds[8][4];
#pragma unroll
        for (int a = 0; a < 8; a++)
#pragma unroll
            for (int k = 0; k < 4; k++) ds[a][k] = 0.f;

#pragma unroll
        for (int ks = 0; ks < 4; ks++) {
            uint32_t gah[4], gal[4];
#pragma unroll
            for (int j = 0; j < 4; j++) {
                gah[j] = smu[gbase + (ks * 8 + j) * 64];
                gal[j] = smu[gbase + (ks * 8 + 4 + j) * 64];
            }
#pragma unroll
            for (int nb = 0; nb < 8; nb++) {
                int nbg = h * 8 + nb;
                uint4 w = __ldg(w4 + W4_WS + (ks * 16 + nbg) * 32 + lane);
                mma16816(ds[nb], gah, w.x, w.y);
                mma16816(ds[nb], gal, w.x, w.y);
                mma16816(ds[nb], gah, w.z, w.w);
            }
        }
#pragma unroll
        for (int nb = 0; nb < 8; nb++) {
            int c = h * 64 + nb * 8 + 2 * q;
            float* r0p = skip + ((size_t)n * SCH + c) * L_OUT;
            float* r1p = skip + ((size_t)n * SCH + c + 1) * L_OUT;
            if (is_first) {
                if (vA && jA >= 0) { r0p[jA] = ds[nb][0]; r1p[jA] = ds[nb][1]; }
                if (vB && jB >= 0) { r0p[jB] = ds[nb][2]; r1p[jB] = ds[nb][3]; }
            } else {
                if (vA && jA >= 0) { redadd(r0p + jA, ds[nb][0]); redadd(r1p + jA, ds[nb][1]); }
                if (vB && jB >= 0) { redadd(r0p + jB, ds[nb][2]); redadd(r1p + jB, ds[nb][3]); }
            }
        }
    }
}

extern "C" void kernel_launch(void* const* d_in, const int* in_sizes, int n_in,
                              void* d_out, int out_size)
{
    const float* x  = (const float*)d_in[0];  // (16, 64, 8192)
    const float* Wd = (const float*)d_in[1];  // (16, 64, 64, 2)
    const float* Wr = (const float*)d_in[2];  // (16, 64, 64)
    const float* Ws = (const float*)d_in[3];  // (16, 128, 64)

    float* out  = (float*)d_out;                                   // (16, 64, 7682)
    float* skip = (float*)d_out + (size_t)N_BATCH * CH * L_OUT;    // (16, 128, 7682)

    float *bufA = nullptr, *bufB = nullptr;
    uint32_t* wimg = nullptr;
    cudaGetSymbolAddress((void**)&bufA, g_bufA);
    cudaGetSymbolAddress((void**)&bufB, g_bufB);
    cudaGetSymbolAddress((void**)&wimg, g_Wimg);
    cudaFuncSetAttribute(wn_mma_kernel,
                         cudaFuncAttributeMaxDynamicSharedMemorySize, SMEM_BYTES);

    // Build per-lane weight fragments once per replay.
    {
        int total = NUM_BLOCKS * IMG_U32;
        prep_weights<<<(total + 255) / 256, 256>>>(Wd, Wr, Ws);
    }

    const int dil[NUM_BLOCKS] = {1, 2, 4, 8, 16, 32, 64, 128,
                                 1, 2, 4, 8, 16, 32, 64, 128};

    const float* src = x;
    int src_stride = L_IN;
    int Lcur = L_IN;

    for (int i = 0; i < NUM_BLOCKS; i++) {
        int d = dil[i];
        int Lnew = Lcur - d;
        float* dst;
        int dst_stride;
        if (i == NUM_BLOCKS - 1) { dst = out; dst_stride = L_OUT; }
        else                     { dst = (i & 1) ? bufB : bufA; dst_stride = L_IN; }

        dim3 grid((Lnew + TILE_P - 1) / TILE_P, N_BATCH);
        wn_mma_kernel<<<grid, NTH, SMEM_BYTES>>>(
            src, src_stride, dst, dst_stride,
            wimg + (size_t)i * IMG_U32,
            skip, Lcur, d, Lnew - L_OUT, (i == 0) ? 1 : 0);

        src = dst;
        src_stride = dst_stride;
        Lcur = Lnew;
    }
}

// round 14
// speedup vs baseline: 3.1973x; 1.0552x over previous
#include <cuda_runtime.h>
#include <cuda_bf16.h>
#include <cstdint>
#include <math.h>

#define N_BATCH 16
#define CH 64
#define SCH 128
#define L_IN 8192
#define L_OUT 7682
#define NUM_BLOCKS 16
#define TILE_P 128
#define NTH 256

// Ping-pong fp32 residual buffers.
__device__ float g_bufA[(size_t)N_BATCH * CH * L_IN];
__device__ float g_bufB[(size_t)N_BATCH * CH * L_IN];

// Per-block pre-fragmented bf16 weights. uint4 per (region, kstep, nblock, lane):
//   (hi.b0, hi.b1, lo.b0, lo.b1)  -- exact mma.sync m16n8k16 B-fragment regs.
#define IMG_U32 20480
#define W4_WD 0
#define W4_WR 2048
#define W4_WS 3072
__device__ __align__(128) uint32_t g_Wimg[NUM_BLOCKS * IMG_U32];

// ---- shared memory ----
// A tile: 128 rows x 132 u32 (conflict-free ldmatrix, validated).
// G tile: 128 rows x 68 u32 [32 hi | 32 lo | pad4] (R8-validated layout).
#define A_STRIDE_U32 132
#define A_U32 (128 * A_STRIDE_U32)          // 16896
#define G_OFF_U32 A_U32
#define G_STRIDE_U32 68
#define SMEM_BYTES ((A_U32 + 128 * G_STRIDE_U32) * 4)   // 102400

__device__ __forceinline__ uint32_t smem_to_u32(const void* p) {
    uint32_t a;
    asm("{ .reg .u64 t; cvta.to.shared.u64 t, %1; cvt.u32.u64 %0, t; }"
        : "=r"(a) : "l"(p));
    return a;
}

__device__ __forceinline__ void ldm_x4(uint32_t* a, uint32_t saddr) {
    asm volatile("ldmatrix.sync.aligned.m8n8.x4.shared.b16 {%0,%1,%2,%3}, [%4];"
                 : "=r"(a[0]), "=r"(a[1]), "=r"(a[2]), "=r"(a[3]) : "r"(saddr));
}

__device__ __forceinline__ void mma16816(float* d, const uint32_t* a,
                                         uint32_t b0, uint32_t b1) {
    asm volatile(
        "mma.sync.aligned.m16n8k16.row.col.f32.bf16.bf16.f32 "
        "{%0,%1,%2,%3}, {%4,%5,%6,%7}, {%8,%9}, {%0,%1,%2,%3};"
        : "+f"(d[0]), "+f"(d[1]), "+f"(d[2]), "+f"(d[3])
        : "r"(a[0]), "r"(a[1]), "r"(a[2]), "r"(a[3]), "r"(b0), "r"(b1));
}

// Fire-and-forget global float add (REDG): no return-trip latency.
__device__ __forceinline__ void redadd(float* p, float v) {
    asm volatile("red.global.add.f32 [%0], %1;" :: "l"(p), "f"(v) : "memory");
}

__device__ __forceinline__ uint32_t pack2(__nv_bfloat16 a, __nv_bfloat16 b) {
    __nv_bfloat162 t(a, b);   // a -> low halfword
    return *reinterpret_cast<uint32_t*>(&t);
}

__device__ __forceinline__ void split(float x, __nv_bfloat16& h, __nv_bfloat16& l) {
    h = __float2bfloat16(x);
    l = __float2bfloat16(x - __bfloat162float(h));
}

// g = tanh(y) * sigmoid(y), via a = e^{-y}.
__device__ __forceinline__ float gated(float y) {
    float yc = fminf(fmaxf(y, -15.f), 15.f);
    float a = __expf(-yc);
    float a2 = a * a;
    return __fdividef(1.f - a2, (1.f + a2) * (1.f + a));
}

// ---------------- prep: build per-lane B fragments (uint4 layout, validated) ----------------
__global__ void prep_weights(const float* __restrict__ Wd,
                             const float* __restrict__ Wr,
                             const float* __restrict__ Ws)
{
    int idx = blockIdx.x * blockDim.x + threadIdx.x;
    if (idx >= NUM_BLOCKS * IMG_U32) return;
    int b = idx / IMG_U32;
    int r = idx % IMG_U32;
    int f = r >> 2;
    int comp = r & 3;
    int part = comp >> 1;
    int reg = comp & 1;
    float w0, w1;
    if (f < W4_WR) {            // Wd region
        int lane = f & 31, nb = (f >> 5) & 7, ks = (f >> 8) & 7;
        int nn = nb * 8 + (lane >> 2), q = lane & 3;
        int k0 = ks * 16 + 2 * q + reg * 8;   // k = ch*2 + tap
        w0 = Wd[(((size_t)b * CH + nn) * CH + (k0 >> 1)) * 2 + (k0 & 1)];
        w1 = Wd[(((size_t)b * CH + nn) * CH + ((k0 + 1) >> 1)) * 2 + ((k0 + 1) & 1)];
    } else if (f < W4_WS) {     // Wr region
        int ff = f - W4_WR;
        int lane = ff & 31, nb = (ff >> 5) & 7, ks = (ff >> 8) & 3;
        int nn = nb * 8 + (lane >> 2), q = lane & 3;
        int k0 = ks * 16 + 2 * q + reg * 8;
        w0 = Wr[((size_t)b * CH + nn) * CH + k0];
        w1 = Wr[((size_t)b * CH + nn) * CH + k0 + 1];
    } else {                    // Ws region
        int ff = f - W4_WS;
        int lane = ff & 31, nb = (ff >> 5) & 15, ks = (ff >> 9) & 3;
        int nn = nb * 8 + (lane >> 2), q = lane & 3;
        int k0 = ks * 16 + 2 * q + reg * 8;
        w0 = Ws[((size_t)b * SCH + nn) * CH + k0];
        w1 = Ws[((size_t)b * SCH + nn) * CH + k0 + 1];
    }
    __nv_bfloat16 h0 = __float2bfloat16(w0);
    __nv_bfloat16 h1 = __float2bfloat16(w1);
    if (part) {
        h0 = __float2bfloat16(w0 - __bfloat162float(h0));
        h1 = __float2bfloat16(w1 - __bfloat162float(h1));
    }
    g_Wimg[(size_t)b * IMG_U32 + r] = pack2(h0, h1);
}

// ---------------- main block kernel ----------------
// Warp layout: warp w -> M-group m = w&3 (rows 32m..32m+31, two 16-row
// subtiles), N-half nh = w>>2. Each weight fragment is loaded by 4 warps
// (was 8) and reused for 2 M-subtiles.
__global__ void __launch_bounds__(NTH, 2)
wn_mma_kernel(const float* __restrict__ src, int src_stride,
              float* __restrict__ dst, int dst_stride,
              const uint32_t* __restrict__ wimg,
              float* __restrict__ skip,
              int Lcur, int d, int skip_off, int is_first)
{
    extern __shared__ unsigned char smem[];
    uint32_t* smu = reinterpret_cast<uint32_t*>(smem);
    const uint32_t smem_base = smem_to_u32(smem);
    const int tid = threadIdx.x;
    const int warp = tid >> 5, lane = tid & 31;
    const int n = blockIdx.y;
    const int p0 = blockIdx.x * TILE_P;
    const int Lnew = Lcur - d;

    const uint4* w4 = reinterpret_cast<const uint4*>(wimg);
    const float* srcn = src + (size_t)n * CH * src_stride;

    // A-build thread mapping (pipelined with GEMM1, validated R13)
    const int pos = tid & 127, half = tid >> 7;
    const int pld = p0 + pos;
    const bool vld = (pld < Lnew);

    auto build_stage = [&](int g) {
#pragma unroll
        for (int j = 0; j < 4; j++) {
            int ch = 8 * g + 2 * j + half;
            float x0 = vld ? __ldg(srcn + (size_t)ch * src_stride + pld) : 0.f;
            float x1 = vld ? __ldg(srcn + (size_t)ch * src_stride + pld + d) : 0.f;
            __nv_bfloat16 h0, l0, h1, l1;
            split(x0, h0, l0);
            split(x1, h1, l1);
            smu[pos * A_STRIDE_U32 + ch] = pack2(h0, h1);        // k=2ch,2ch+1
            smu[pos * A_STRIDE_U32 + 64 + ch] = pack2(l0, l1);
        }
    };

    const int m = warp & 3, nh = warp >> 2;
    const int r = lane >> 2, q = lane & 3;

    // ================= GEMM1 pipelined with A-build =================
    float d1[2][4][4];
#pragma unroll
    for (int s = 0; s < 2; s++)
#pragma unroll
        for (int a = 0; a < 4; a++)
#pragma unroll
            for (int k = 0; k < 4; k++) d1[s][a][k] = 0.f;

    build_stage(0);
    __syncthreads();

    {
        const uint32_t a_row0 = smem_base + (32 * m + (lane & 15)) * (A_STRIDE_U32 * 4)
                              + ((lane >> 4) * 16);
        const uint32_t a_row1 = a_row0 + 16 * (A_STRIDE_U32 * 4);
        uint4 wcur[4];
#pragma unroll
        for (int j = 0; j < 4; j++)
            wcur[j] = __ldg(w4 + W4_WD + (nh * 4 + j) * 32 + lane);
#pragma unroll
        for (int ks = 0; ks < 8; ks++) {
            if (ks < 7) build_stage(ks + 1);
            uint4 wnxt[4];
            if (ks < 7) {
#pragma unroll
                for (int j = 0; j < 4; j++)
                    wnxt[j] = __ldg(w4 + W4_WD + ((ks + 1) * 8 + nh * 4 + j) * 32 + lane);
            }
            uint32_t ah0[4], al0[4], ah1[4], al1[4];
            ldm_x4(ah0, a_row0 + ks * 32);
            ldm_x4(al0, a_row0 + 256 + ks * 32);
            ldm_x4(ah1, a_row1 + ks * 32);
            ldm_x4(al1, a_row1 + 256 + ks * 32);
#pragma unroll
            for (int j = 0; j < 4; j++) {
                mma16816(d1[0][j], ah0, wcur[j].x, wcur[j].y);
                mma16816(d1[0][j], al0, wcur[j].x, wcur[j].y);
                mma16816(d1[0][j], ah0, wcur[j].z, wcur[j].w);
                mma16816(d1[1][j], ah1, wcur[j].x, wcur[j].y);
                mma16816(d1[1][j], al1, wcur[j].x, wcur[j].y);
                mma16816(d1[1][j], ah1, wcur[j].z, wcur[j].w);
            }
            if (ks < 7) {
#pragma unroll
                for (int j = 0; j < 4; j++) wcur[j] = wnxt[j];
            }
            __syncthreads();
        }
    }

    // ---- epilogue 1: gate, hi/lo split, write G to shared ldmatrix layout ----
    // d-frag (row0=32m+16s+r, cols 2q/2q+1 of n-block nh*4+j) -> G u32 col nh*16+j*4+q
#pragma unroll
    for (int s = 0; s < 2; s++) {
#pragma unroll
        for (int j = 0; j < 4; j++) {
            float g0 = gated(d1[s][j][0]), g1 = gated(d1[s][j][1]);
            float g2 = gated(d1[s][j][2]), g3 = gated(d1[s][j][3]);
            __nv_bfloat16 h0, l0, h1, l1, h2, l2, h3, l3;
            split(g0, h0, l0); split(g1, h1, l1);
            split(g2, h2, l2); split(g3, h3, l3);
            int col = nh * 16 + j * 4 + q;
            int rowA = 32 * m + 16 * s + r;
            smu[G_OFF_U32 + rowA * G_STRIDE_U32 + col] = pack2(h0, h1);
            smu[G_OFF_U32 + rowA * G_STRIDE_U32 + 32 + col] = pack2(l0, l1);
            smu[G_OFF_U32 + (rowA + 8) * G_STRIDE_U32 + col] = pack2(h2, h3);
            smu[G_OFF_U32 + (rowA + 8) * G_STRIDE_U32 + 32 + col] = pack2(l2, l3);
        }
    }
    __syncthreads();   // exchange G across N-half partner warps

    const uint32_t g_row0 = smem_base + G_OFF_U32 * 4
                          + (32 * m + (lane & 15)) * (G_STRIDE_U32 * 4)
                          + ((lane >> 4) * 16);
    const uint32_t g_row1 = g_row0 + 16 * (G_STRIDE_U32 * 4);

    const int pA0 = p0 + 32 * m + r;          // sub 0 rows: pA0, pA0+8
    const int pA1 = pA0 + 16;                 // sub 1 rows: pA1, pA1+8

    // ================= GEMM2a: res[128, nh-half of 64] + direct store =================
    {
        float dr[2][4][4];
#pragma unroll
        for (int s = 0; s < 2; s++)
#pragma unroll
            for (int a = 0; a < 4; a++)
#pragma unroll
                for (int k = 0; k < 4; k++) dr[s][a][k] = 0.f;

#pragma unroll
        for (int ks = 0; ks < 4; ks++) {
            uint32_t ah0[4], al0[4], ah1[4], al1[4];
            ldm_x4(ah0, g_row0 + ks * 32);
            ldm_x4(al0, g_row0 + 128 + ks * 32);
            ldm_x4(ah1, g_row1 + ks * 32);
            ldm_x4(al1, g_row1 + 128 + ks * 32);
#pragma unroll
            for (int j = 0; j < 4; j++) {
                uint4 w = __ldg(w4 + W4_WR + (ks * 8 + nh * 4 + j) * 32 + lane);
                mma16816(dr[0][j], ah0, w.x, w.y);
                mma16816(dr[0][j], al0, w.x, w.y);
                mma16816(dr[0][j], ah0, w.z, w.w);
                mma16816(dr[1][j], ah1, w.x, w.y);
                mma16816(dr[1][j], al1, w.x, w.y);
                mma16816(dr[1][j], ah1, w.z, w.w);
            }
        }
#pragma unroll
        for (int s = 0; s < 2; s++) {
            int pA = (s == 0) ? pA0 : pA1;
            int pB = pA + 8;
            bool vA = (pA < Lnew), vB = (pB < Lnew);
#pragma unroll
            for (int j = 0; j < 4; j++) {
                int c = (nh * 4 + j) * 8 + 2 * q;
                if (vA) {
                    dst[((size_t)n * CH + c) * dst_stride + pA] =
                        dr[s][j][0] + __ldg(srcn + (size_t)c * src_stride + pA + d);
                    dst[((size_t)n * CH + c + 1) * dst_stride + pA] =
                        dr[s][j][1] + __ldg(srcn + (size_t)(c + 1) * src_stride + pA + d);
                }
                if (vB) {
                    dst[((size_t)n * CH + c) * dst_stride + pB] =
                        dr[s][j][2] + __ldg(srcn + (size_t)c * src_stride + pB + d);
                    dst[((size_t)n * CH + c + 1) * dst_stride + pB] =
                        dr[s][j][3] + __ldg(srcn + (size_t)(c + 1) * src_stride + pB + d);
                }
            }
        }
    }

    // ================= GEMM2b: skip[128, nh-half of 128] via REDG =================
#pragma unroll
    for (int h = 0; h < 2; h++) {
        float ds[2][4][4];
#pragma unroll
        for (int s = 0; s < 2; s++)
#pragma unroll
            for (int a = 0; a < 4; a++)
#pragma unroll
                for (int k = 0; k < 4; k++) ds[s][a][k] = 0.f;

#pragma unroll
        for (int ks = 0; ks < 4; ks++) {
            uint32_t ah0[4], al0[4], ah1[4], al1[4];
            ldm_x4(ah0, g_row0 + ks * 32);
            ldm_x4(al0, g_row0 + 128 + ks * 32);
            ldm_x4(ah1, g_row1 + ks * 32);
            ldm_x4(al1, g_row1 + 128 + ks * 32);
#pragma unroll
            for (int j = 0; j < 4; j++) {
                int nbg = nh * 8 + h * 4 + j;
                uint4 w = __ldg(w4 + W4_WS + (ks * 16 + nbg) * 32 + lane);
                mma16816(ds[0][j], ah0, w.x, w.y);
                mma16816(ds[0][j], al0, w.x, w.y);
                mma16816(ds[0][j], ah0, w.z, w.w);
                mma16816(ds[1][j], ah1, w.x, w.y);
                mma16816(ds[1][j], al1, w.x, w.y);
                mma16816(ds[1][j], ah1, w.z, w.w);
            }
        }
#pragma unroll
        for (int s = 0; s < 2; s++) {
            int pA = (s == 0) ? pA0 : pA1;
            int pB = pA + 8;
            int jA = pA - skip_off, jB = pB - skip_off;
            bool vA = (pA < Lnew), vB = (pB < Lnew);
#pragma unroll
            for (int j = 0; j < 4; j++) {
                int c = (nh * 8 + h * 4 + j) * 8 + 2 * q;
                float* r0p = skip + ((size_t)n * SCH + c) * L_OUT;
                float* r1p = skip + ((size_t)n * SCH + c + 1) * L_OUT;
                if (is_first) {
                    if (vA && jA >= 0) { r0p[jA] = ds[s][j][0]; r1p[jA] = ds[s][j][1]; }
                    if (vB && jB >= 0) { r0p[jB] = ds[s][j][2]; r1p[jB] = ds[s][j][3]; }
                } else {
                    if (vA && jA >= 0) { redadd(r0p + jA, ds[s][j][0]); redadd(r1p + jA, ds[s][j][1]); }
                    if (vB && jB >= 0) { redadd(r0p + jB, ds[s][j][2]); redadd(r1p + jB, ds[s][j][3]); }
                }
            }
        }
    }
}

extern "C" void kernel_launch(void* const* d_in, const int* in_sizes, int n_in,
                              void* d_out, int out_size)
{
    const float* x  = (const float*)d_in[0];  // (16, 64, 8192)
    const float* Wd = (const float*)d_in[1];  // (16, 64, 64, 2)
    const float* Wr = (const float*)d_in[2];  // (16, 64, 64)
    const float* Ws = (const float*)d_in[3];  // (16, 128, 64)

    float* out  = (float*)d_out;                                   // (16, 64, 7682)
    float* skip = (float*)d_out + (size_t)N_BATCH * CH * L_OUT;    // (16, 128, 7682)

    float *bufA = nullptr, *bufB = nullptr;
    uint32_t* wimg = nullptr;
    cudaGetSymbolAddress((void**)&bufA, g_bufA);
    cudaGetSymbolAddress((void**)&bufB, g_bufB);
    cudaGetSymbolAddress((void**)&wimg, g_Wimg);
    cudaFuncSetAttribute(wn_mma_kernel,
                         cudaFuncAttributeMaxDynamicSharedMemorySize, SMEM_BYTES);

    // Build per-lane weight fragments once per replay.
    {
        int total = NUM_BLOCKS * IMG_U32;
        prep_weights<<<(total + 255) / 256, 256>>>(Wd, Wr, Ws);
    }

    const int dil[NUM_BLOCKS] = {1, 2, 4, 8, 16, 32, 64, 128,
                                 1, 2, 4, 8, 16, 32, 64, 128};

    const float* src = x;
    int src_stride = L_IN;
    int Lcur = L_IN;

    for (int i = 0; i < NUM_BLOCKS; i++) {
        int d = dil[i];
        int Lnew = Lcur - d;
        float* dst;
        int dst_stride;
        if (i == NUM_BLOCKS - 1) { dst = out; dst_stride = L_OUT; }
        else                     { dst = (i & 1) ? bufB : bufA; dst_stride = L_IN; }

        dim3 grid((Lnew + TILE_P - 1) / TILE_P, N_BATCH);
        wn_mma_kernel<<<grid, NTH, SMEM_BYTES>>>(
            src, src_stride, dst, dst_stride,
            wimg + (size_t)i * IMG_U32,
            skip, Lcur, d, Lnew - L_OUT, (i == 0) ? 1 : 0);

        src = dst;
        src_stride = dst_stride;
        Lcur = Lnew;
    }
}